// round 2
// baseline (speedup 1.0000x reference)
#include <cuda_runtime.h>
#include <cstdint>

#define DD 128
#define NODES_MAX 50000
#define NGRAPH 64
#define NCLASS 32
#define BM 128
#define SA 132                       // padded row stride for transposed smem tiles
#define SMEM_FLOATS (2*DD*DD + DD*SA)
#define SMEM_BYTES (SMEM_FLOATS * 4)

__device__ float g_bufA[NODES_MAX * DD];
__device__ float g_bufB[NODES_MAX * DD];
__device__ float g_pool[NGRAPH * DD];
__device__ float g_cnt[NGRAPH];
__device__ float g_scratch[NGRAPH * DD + NGRAPH * NCLASS];
__device__ int   g_is64;

// ---------- packed f32x2 helpers ----------
__device__ __forceinline__ unsigned long long splat2(float x) {
    unsigned long long r;
    asm("mov.b64 %0, {%1, %1};" : "=l"(r) : "f"(x));
    return r;
}
__device__ __forceinline__ void fma2(unsigned long long& acc, unsigned long long a, unsigned long long b) {
    asm("fma.rn.f32x2 %0, %1, %2, %0;" : "+l"(acc) : "l"(a), "l"(b));
}
__device__ __forceinline__ float lo32(unsigned long long v) { return __uint_as_float((unsigned)(v & 0xffffffffull)); }
__device__ __forceinline__ float hi32(unsigned long long v) { return __uint_as_float((unsigned)(v >> 32)); }

// ---------- dtype detection: int64 viewed as int32 has odd words == 0 ----------
__global__ void detect_kernel(const int* __restrict__ idx32) {
    if (threadIdx.x == 0 && blockIdx.x == 0) {
        int is64 = 1;
        #pragma unroll 1
        for (int i = 1; i < 128; i += 2)
            if (idx32[i] != 0) { is64 = 0; break; }
        g_is64 = is64;
    }
}

__device__ __forceinline__ int load_idx(const void* p, int i, int is64) {
    if (is64) return (int)((const long long*)p)[i];
    return ((const int*)p)[i];
}

// ---------- copy: agg = h ----------
__global__ void copy_kernel(float* __restrict__ dst, const float* __restrict__ src, int n4) {
    int i = blockIdx.x * blockDim.x + threadIdx.x;
    if (i < n4) ((float4*)dst)[i] = ((const float4*)src)[i];
}

// ---------- scatter-add: agg[dst] += h[src], one warp per edge ----------
__global__ void scatter_kernel(const float* __restrict__ h, const void* __restrict__ ei,
                               float* __restrict__ agg, int ne, int n) {
    int e = (blockIdx.x * blockDim.x + threadIdx.x) >> 5;
    int lane = threadIdx.x & 31;
    if (e >= ne) return;
    const int is64 = g_is64;
    int s = load_idx(ei, e, is64);
    int d = load_idx(ei, ne + e, is64);
    if ((unsigned)s >= (unsigned)n || (unsigned)d >= (unsigned)n) return;
    float4 v = *(const float4*)(h + (size_t)s * DD + lane * 4);
    float* p = agg + (size_t)d * DD + lane * 4;
    atomicAdd(p + 0, v.x);
    atomicAdd(p + 1, v.y);
    atomicAdd(p + 2, v.z);
    atomicAdd(p + 3, v.w);
}

// ---------- fused MLP: out = [relu]( relu(in@W1+b1) @ W2 + b2 ) ----------
__global__ void __launch_bounds__(256, 1)
mlp_kernel(const float* __restrict__ in, const float* __restrict__ w1,
           const float* __restrict__ b1, const float* __restrict__ w2,
           const float* __restrict__ b2, float* __restrict__ out,
           int n, int relu_out)
{
    extern __shared__ float sm[];
    float* w1s = sm;                 // DD*DD
    float* w2s = sm + DD * DD;       // DD*DD
    float* ts  = sm + 2 * DD * DD;   // transposed tile: ts[k*SA + r]

    const int tid = threadIdx.x;

    // load both weight matrices (16384 floats each)
    #pragma unroll
    for (int i = 0; i < DD * DD; i += 1024) {
        int idx = i + tid * 4;
        *(float4*)(w1s + idx) = *(const float4*)(w1 + idx);
        *(float4*)(w2s + idx) = *(const float4*)(w2 + idx);
    }

    // load input tile transposed: ts[c][r]
    const int row0 = blockIdx.x * BM;
    for (int i = tid; i < BM * (DD / 4); i += 256) {
        int r = i >> 5;             // DD/4 == 32 float4 per row
        int c = (i & 31) * 4;
        float4 v = make_float4(0.f, 0.f, 0.f, 0.f);
        if (row0 + r < n) v = *(const float4*)(in + (size_t)(row0 + r) * DD + c);
        ts[(c + 0) * SA + r] = v.x;
        ts[(c + 1) * SA + r] = v.y;
        ts[(c + 2) * SA + r] = v.z;
        ts[(c + 3) * SA + r] = v.w;
    }
    __syncthreads();

    const int rb = (tid & 15) * 8;   // row offset within tile
    const int cb = (tid >> 4) * 8;   // col offset within tile

    unsigned long long acc[4][8];

    // ================= stage 1: z = relu(in @ W1 + b1) =================
    #pragma unroll
    for (int i = 0; i < 4; i++)
        #pragma unroll
        for (int j = 0; j < 8; j++) acc[i][j] = 0ull;

    #pragma unroll 2
    for (int k = 0; k < DD; ++k) {
        const float* tk = ts + k * SA + rb;
        ulonglong2 aA = *(const ulonglong2*)(tk);
        ulonglong2 aB = *(const ulonglong2*)(tk + 4);
        unsigned long long ap[4] = { aA.x, aA.y, aB.x, aB.y };
        const float4 bv0 = *(const float4*)(w1s + k * DD + cb);
        const float4 bv1 = *(const float4*)(w1s + k * DD + cb + 4);
        unsigned long long bs[8] = { splat2(bv0.x), splat2(bv0.y), splat2(bv0.z), splat2(bv0.w),
                                     splat2(bv1.x), splat2(bv1.y), splat2(bv1.z), splat2(bv1.w) };
        #pragma unroll
        for (int i = 0; i < 4; i++)
            #pragma unroll
            for (int j = 0; j < 8; j++)
                fma2(acc[i][j], ap[i], bs[j]);
    }
    __syncthreads();   // all threads done reading ts

    // epilogue 1: bias + relu, write z transposed back into ts
    #pragma unroll
    for (int j = 0; j < 8; ++j) {
        float bj = b1[cb + j];
        float4 v0, v1;
        v0.x = fmaxf(lo32(acc[0][j]) + bj, 0.f);
        v0.y = fmaxf(hi32(acc[0][j]) + bj, 0.f);
        v0.z = fmaxf(lo32(acc[1][j]) + bj, 0.f);
        v0.w = fmaxf(hi32(acc[1][j]) + bj, 0.f);
        v1.x = fmaxf(lo32(acc[2][j]) + bj, 0.f);
        v1.y = fmaxf(hi32(acc[2][j]) + bj, 0.f);
        v1.z = fmaxf(lo32(acc[3][j]) + bj, 0.f);
        v1.w = fmaxf(hi32(acc[3][j]) + bj, 0.f);
        *(float4*)(ts + (cb + j) * SA + rb)     = v0;
        *(float4*)(ts + (cb + j) * SA + rb + 4) = v1;
    }
    __syncthreads();

    // ================= stage 2: h = z @ W2 + b2 (+relu) =================
    #pragma unroll
    for (int i = 0; i < 4; i++)
        #pragma unroll
        for (int j = 0; j < 8; j++) acc[i][j] = 0ull;

    #pragma unroll 2
    for (int k = 0; k < DD; ++k) {
        const float* tk = ts + k * SA + rb;
        ulonglong2 aA = *(const ulonglong2*)(tk);
        ulonglong2 aB = *(const ulonglong2*)(tk + 4);
        unsigned long long ap[4] = { aA.x, aA.y, aB.x, aB.y };
        const float4 bv0 = *(const float4*)(w2s + k * DD + cb);
        const float4 bv1 = *(const float4*)(w2s + k * DD + cb + 4);
        unsigned long long bs[8] = { splat2(bv0.x), splat2(bv0.y), splat2(bv0.z), splat2(bv0.w),
                                     splat2(bv1.x), splat2(bv1.y), splat2(bv1.z), splat2(bv1.w) };
        #pragma unroll
        for (int i = 0; i < 4; i++)
            #pragma unroll
            for (int j = 0; j < 8; j++)
                fma2(acc[i][j], ap[i], bs[j]);
    }

    // epilogue 2: bias (+relu), store to global
    float bb[8];
    #pragma unroll
    for (int j = 0; j < 8; ++j) bb[j] = b2[cb + j];

    #pragma unroll
    for (int i2 = 0; i2 < 4; ++i2) {
        float o0[8], o1[8];
        #pragma unroll
        for (int j = 0; j < 8; ++j) {
            o0[j] = lo32(acc[i2][j]) + bb[j];
            o1[j] = hi32(acc[i2][j]) + bb[j];
            if (relu_out) { o0[j] = fmaxf(o0[j], 0.f); o1[j] = fmaxf(o1[j], 0.f); }
        }
        int r0g = row0 + rb + 2 * i2;
        if (r0g < n) {
            *(float4*)(out + (size_t)r0g * DD + cb)     = make_float4(o0[0], o0[1], o0[2], o0[3]);
            *(float4*)(out + (size_t)r0g * DD + cb + 4) = make_float4(o0[4], o0[5], o0[6], o0[7]);
        }
        if (r0g + 1 < n) {
            *(float4*)(out + (size_t)(r0g + 1) * DD + cb)     = make_float4(o1[0], o1[1], o1[2], o1[3]);
            *(float4*)(out + (size_t)(r0g + 1) * DD + cb + 4) = make_float4(o1[4], o1[5], o1[6], o1[7]);
        }
    }
}

// ---------- pooling ----------
__global__ void zero_pool_kernel(float* pool, float* cnt) {
    int i = blockIdx.x * blockDim.x + threadIdx.x;
    if (i < NGRAPH * DD) pool[i] = 0.f;
    if (i < NGRAPH) cnt[i] = 0.f;
}

__global__ void pool_kernel(const float* __restrict__ h, const void* __restrict__ batch,
                            float* __restrict__ pool, float* __restrict__ cnt, int n) {
    int node = (blockIdx.x * blockDim.x + threadIdx.x) >> 5;
    int lane = threadIdx.x & 31;
    if (node >= n) return;
    int g = load_idx(batch, node, g_is64);
    if ((unsigned)g >= (unsigned)NGRAPH) return;
    float4 v = *(const float4*)(h + (size_t)node * DD + lane * 4);
    float* p = pool + g * DD + lane * 4;
    atomicAdd(p + 0, v.x);
    atomicAdd(p + 1, v.y);
    atomicAdd(p + 2, v.z);
    atomicAdd(p + 3, v.w);
    if (lane == 0) atomicAdd(cnt + g, 1.0f);
}

// ---------- finalize: pooled mean + logits ----------
__global__ void finalize_kernel(const float* __restrict__ pool, const float* __restrict__ cnt,
                                const float* __restrict__ wlin, const float* __restrict__ blin,
                                float* __restrict__ out_pooled, float* __restrict__ out_logits) {
    __shared__ float ps[DD];
    int g = blockIdx.x;
    int t = threadIdx.x;
    float c = fmaxf(cnt[g], 1.0f);
    float v = pool[g * DD + t] / c;
    ps[t] = v;
    out_pooled[g * DD + t] = v;                 // pooled output [64,128]
    __syncthreads();
    if (t < NCLASS) {
        float s = blin[t];
        #pragma unroll 4
        for (int k = 0; k < DD; ++k) s += ps[k] * wlin[k * NCLASS + t];
        out_logits[g * NCLASS + t] = s;         // logits output [64,32]
    }
}

extern "C" void kernel_launch(void* const* d_in, const int* in_sizes, int n_in,
                              void* d_out, int out_size) {
    const float* x     = (const float*)d_in[0];
    const void*  ei    = d_in[1];
    const void*  batch = d_in[2];
    const float* w1    = (const float*)d_in[3];
    const float* b1    = (const float*)d_in[4];
    const float* w2    = (const float*)d_in[5];
    const float* b2    = (const float*)d_in[6];
    const float* wlin  = (const float*)d_in[7];
    const float* blin  = (const float*)d_in[8];
    float* out = (float*)d_out;

    int n  = in_sizes[0] / DD;      // 50000 nodes
    int ne = in_sizes[1] / 2;       // 640000 edges
    if (n > NODES_MAX) n = NODES_MAX;

    float *pA, *pB, *pPool, *pCnt, *pScratch;
    cudaGetSymbolAddress((void**)&pA, g_bufA);
    cudaGetSymbolAddress((void**)&pB, g_bufB);
    cudaGetSymbolAddress((void**)&pPool, g_pool);
    cudaGetSymbolAddress((void**)&pCnt, g_cnt);
    cudaGetSymbolAddress((void**)&pScratch, g_scratch);

    cudaFuncSetAttribute(mlp_kernel, cudaFuncAttributeMaxDynamicSharedMemorySize, SMEM_BYTES);

    const int n4 = n * DD / 4;
    const int copy_grid    = (n4 + 255) / 256;
    const int scatter_grid = (ne * 32 + 255) / 256;
    const int mlp_grid     = (n + BM - 1) / BM;
    const int pool_grid    = (n * 32 + 255) / 256;

    detect_kernel<<<1, 32>>>((const int*)ei);

    const float* hcur = x;
    for (int L = 0; L < 4; ++L) {
        copy_kernel<<<copy_grid, 256>>>(pB, hcur, n4);
        scatter_kernel<<<scatter_grid, 256>>>(hcur, ei, pB, ne, n);
        mlp_kernel<<<mlp_grid, 256, SMEM_BYTES>>>(
            pB, w1 + (size_t)L * DD * DD, b1 + (size_t)L * DD,
            w2 + (size_t)L * DD * DD, b2 + (size_t)L * DD,
            pA, n, (L < 3) ? 1 : 0);
        hcur = pA;
    }

    zero_pool_kernel<<<(NGRAPH * DD + 255) / 256, 256>>>(pPool, pCnt);
    pool_kernel<<<pool_grid, 256>>>(pA, batch, pPool, pCnt, n);

    // output layout adaptive to out_size: expected 10240 = 64*128 pooled || 64*32 logits
    float* out_pooled = pScratch;
    float* out_logits = pScratch + NGRAPH * DD;
    if (out_size >= NGRAPH * DD + NGRAPH * NCLASS) {
        out_pooled = out;
        out_logits = out + NGRAPH * DD;
    } else if (out_size == NGRAPH * NCLASS) {
        out_logits = out;
    } else if (out_size == NGRAPH * DD) {
        out_pooled = out;
    }
    finalize_kernel<<<NGRAPH, DD>>>(pPool, pCnt, wlin, blin, out_pooled, out_logits);
}

// round 3
// speedup vs baseline: 1.3644x; 1.3644x over previous
#include <cuda_runtime.h>
#include <cstdint>

#define DD 128
#define NODES_MAX 50000
#define NGRAPH 64
#define NCLASS 32
#define BM 128
#define TB 512
#define SA 132                       // padded row stride for transposed smem tiles
#define SMEM_FLOATS (2*DD*DD + DD*SA)
#define SMEM_BYTES (SMEM_FLOATS * 4)

__device__ float g_bufA[NODES_MAX * DD];
__device__ float g_bufB[NODES_MAX * DD];
__device__ float g_pool[NGRAPH * DD];
__device__ float g_cnt[NGRAPH];
__device__ float g_scratch[NGRAPH * DD + NGRAPH * NCLASS];
__device__ int   g_is64;

// ---------- packed f32x2 helpers ----------
__device__ __forceinline__ unsigned long long splat2(float x) {
    unsigned long long r;
    asm("mov.b64 %0, {%1, %1};" : "=l"(r) : "f"(x));
    return r;
}
__device__ __forceinline__ void fma2(unsigned long long& acc, unsigned long long a, unsigned long long b) {
    asm("fma.rn.f32x2 %0, %1, %2, %0;" : "+l"(acc) : "l"(a), "l"(b));
}
__device__ __forceinline__ float lo32(unsigned long long v) { return __uint_as_float((unsigned)(v & 0xffffffffull)); }
__device__ __forceinline__ float hi32(unsigned long long v) { return __uint_as_float((unsigned)(v >> 32)); }

__device__ __forceinline__ void red_add_v4(float* p, float4 v) {
    asm volatile("red.global.add.v4.f32 [%0], {%1, %2, %3, %4};"
                 :: "l"(p), "f"(v.x), "f"(v.y), "f"(v.z), "f"(v.w) : "memory");
}

// ---------- dtype detection: int64 viewed as int32 has odd words == 0 ----------
__global__ void detect_kernel(const int* __restrict__ idx32) {
    if (threadIdx.x == 0 && blockIdx.x == 0) {
        int is64 = 1;
        #pragma unroll 1
        for (int i = 1; i < 128; i += 2)
            if (idx32[i] != 0) { is64 = 0; break; }
        g_is64 = is64;
    }
}

__device__ __forceinline__ int load_idx(const void* p, int i, int is64) {
    if (is64) return (int)((const long long*)p)[i];
    return ((const int*)p)[i];
}

// ---------- scatter-add: agg[dst] += h[src], one warp per edge, red.v4 ----------
__global__ void scatter_kernel(const float* __restrict__ h, const void* __restrict__ ei,
                               float* __restrict__ agg, int ne, int n) {
    int e = (blockIdx.x * blockDim.x + threadIdx.x) >> 5;
    int lane = threadIdx.x & 31;
    if (e >= ne) return;
    const int is64 = g_is64;
    int s = load_idx(ei, e, is64);
    int d = load_idx(ei, ne + e, is64);
    if ((unsigned)s >= (unsigned)n || (unsigned)d >= (unsigned)n) return;
    float4 v = *(const float4*)(h + (size_t)s * DD + lane * 4);
    red_add_v4(agg + (size_t)d * DD + lane * 4, v);
}

// ---------- fused MLP: out = [relu]( relu(in@W1+b1) @ W2 + b2 ), 512 threads ----------
__global__ void __launch_bounds__(TB, 1)
mlp_kernel(const float* __restrict__ in, const float* __restrict__ w1,
           const float* __restrict__ b1, const float* __restrict__ w2,
           const float* __restrict__ b2, float* __restrict__ out,
           int n, int relu_out)
{
    extern __shared__ float sm[];
    float* w1s = sm;                 // DD*DD
    float* w2s = sm + DD * DD;       // DD*DD
    float* ts  = sm + 2 * DD * DD;   // transposed tile: ts[k*SA + r]

    const int tid = threadIdx.x;

    // load both weight matrices (16384 floats each)
    #pragma unroll
    for (int i = 0; i < DD * DD; i += TB * 4) {
        int idx = i + tid * 4;
        *(float4*)(w1s + idx) = *(const float4*)(w1 + idx);
        *(float4*)(w2s + idx) = *(const float4*)(w2 + idx);
    }

    // load input tile transposed: ts[c][r]
    const int row0 = blockIdx.x * BM;
    #pragma unroll
    for (int i = tid; i < BM * (DD / 4); i += TB) {
        int r = i >> 5;             // DD/4 == 32 float4 per row
        int c = (i & 31) * 4;
        float4 v = make_float4(0.f, 0.f, 0.f, 0.f);
        if (row0 + r < n) v = *(const float4*)(in + (size_t)(row0 + r) * DD + c);
        ts[(c + 0) * SA + r] = v.x;
        ts[(c + 1) * SA + r] = v.y;
        ts[(c + 2) * SA + r] = v.z;
        ts[(c + 3) * SA + r] = v.w;
    }
    __syncthreads();

    const int rb = (tid & 15) * 8;   // row offset within tile (8 rows = 4 pairs)
    const int cb = (tid >> 4) * 4;   // col offset within tile (4 cols)

    unsigned long long acc[4][4];

    // ================= stage 1: z = relu(in @ W1 + b1) =================
    #pragma unroll
    for (int i = 0; i < 4; i++)
        #pragma unroll
        for (int j = 0; j < 4; j++) acc[i][j] = 0ull;

    #pragma unroll 4
    for (int k = 0; k < DD; ++k) {
        const float* tk = ts + k * SA + rb;
        ulonglong2 aA = *(const ulonglong2*)(tk);
        ulonglong2 aB = *(const ulonglong2*)(tk + 4);
        unsigned long long ap[4] = { aA.x, aA.y, aB.x, aB.y };
        const float4 bv = *(const float4*)(w1s + k * DD + cb);
        unsigned long long bs[4] = { splat2(bv.x), splat2(bv.y), splat2(bv.z), splat2(bv.w) };
        #pragma unroll
        for (int i = 0; i < 4; i++)
            #pragma unroll
            for (int j = 0; j < 4; j++)
                fma2(acc[i][j], ap[i], bs[j]);
    }
    __syncthreads();   // all threads done reading ts

    // epilogue 1: bias + relu, write z transposed back into ts
    #pragma unroll
    for (int j = 0; j < 4; ++j) {
        float bj = b1[cb + j];
        float4 v0, v1;
        v0.x = fmaxf(lo32(acc[0][j]) + bj, 0.f);
        v0.y = fmaxf(hi32(acc[0][j]) + bj, 0.f);
        v0.z = fmaxf(lo32(acc[1][j]) + bj, 0.f);
        v0.w = fmaxf(hi32(acc[1][j]) + bj, 0.f);
        v1.x = fmaxf(lo32(acc[2][j]) + bj, 0.f);
        v1.y = fmaxf(hi32(acc[2][j]) + bj, 0.f);
        v1.z = fmaxf(lo32(acc[3][j]) + bj, 0.f);
        v1.w = fmaxf(hi32(acc[3][j]) + bj, 0.f);
        *(float4*)(ts + (cb + j) * SA + rb)     = v0;
        *(float4*)(ts + (cb + j) * SA + rb + 4) = v1;
    }
    __syncthreads();

    // ================= stage 2: h = z @ W2 + b2 (+relu) =================
    #pragma unroll
    for (int i = 0; i < 4; i++)
        #pragma unroll
        for (int j = 0; j < 4; j++) acc[i][j] = 0ull;

    #pragma unroll 4
    for (int k = 0; k < DD; ++k) {
        const float* tk = ts + k * SA + rb;
        ulonglong2 aA = *(const ulonglong2*)(tk);
        ulonglong2 aB = *(const ulonglong2*)(tk + 4);
        unsigned long long ap[4] = { aA.x, aA.y, aB.x, aB.y };
        const float4 bv = *(const float4*)(w2s + k * DD + cb);
        unsigned long long bs[4] = { splat2(bv.x), splat2(bv.y), splat2(bv.z), splat2(bv.w) };
        #pragma unroll
        for (int i = 0; i < 4; i++)
            #pragma unroll
            for (int j = 0; j < 4; j++)
                fma2(acc[i][j], ap[i], bs[j]);
    }

    // epilogue 2: bias (+relu), store to global
    float bb[4];
    #pragma unroll
    for (int j = 0; j < 4; ++j) bb[j] = b2[cb + j];

    #pragma unroll
    for (int i2 = 0; i2 < 4; ++i2) {
        float o0[4], o1[4];
        #pragma unroll
        for (int j = 0; j < 4; ++j) {
            o0[j] = lo32(acc[i2][j]) + bb[j];
            o1[j] = hi32(acc[i2][j]) + bb[j];
            if (relu_out) { o0[j] = fmaxf(o0[j], 0.f); o1[j] = fmaxf(o1[j], 0.f); }
        }
        int r0g = row0 + rb + 2 * i2;
        if (r0g < n)
            *(float4*)(out + (size_t)r0g * DD + cb) = make_float4(o0[0], o0[1], o0[2], o0[3]);
        if (r0g + 1 < n)
            *(float4*)(out + (size_t)(r0g + 1) * DD + cb) = make_float4(o1[0], o1[1], o1[2], o1[3]);
    }
}

// ---------- pooling ----------
__global__ void zero_pool_kernel(float* pool, float* cnt) {
    int i = blockIdx.x * blockDim.x + threadIdx.x;
    if (i < NGRAPH * DD) pool[i] = 0.f;
    if (i < NGRAPH) cnt[i] = 0.f;
}

__global__ void pool_kernel(const float* __restrict__ h, const void* __restrict__ batch,
                            float* __restrict__ pool, float* __restrict__ cnt, int n) {
    int node = (blockIdx.x * blockDim.x + threadIdx.x) >> 5;
    int lane = threadIdx.x & 31;
    if (node >= n) return;
    int g = load_idx(batch, node, g_is64);
    if ((unsigned)g >= (unsigned)NGRAPH) return;
    float4 v = *(const float4*)(h + (size_t)node * DD + lane * 4);
    red_add_v4(pool + g * DD + lane * 4, v);
    if (lane == 0) atomicAdd(cnt + g, 1.0f);
}

// ---------- finalize: pooled mean + logits ----------
__global__ void finalize_kernel(const float* __restrict__ pool, const float* __restrict__ cnt,
                                const float* __restrict__ wlin, const float* __restrict__ blin,
                                float* __restrict__ out_pooled, float* __restrict__ out_logits) {
    __shared__ float ps[DD];
    int g = blockIdx.x;
    int t = threadIdx.x;
    float c = fmaxf(cnt[g], 1.0f);
    float v = pool[g * DD + t] / c;
    ps[t] = v;
    out_pooled[g * DD + t] = v;                 // pooled output [64,128]
    __syncthreads();
    if (t < NCLASS) {
        float s = blin[t];
        #pragma unroll 4
        for (int k = 0; k < DD; ++k) s += ps[k] * wlin[k * NCLASS + t];
        out_logits[g * NCLASS + t] = s;         // logits output [64,32]
    }
}

extern "C" void kernel_launch(void* const* d_in, const int* in_sizes, int n_in,
                              void* d_out, int out_size) {
    const float* x     = (const float*)d_in[0];
    const void*  ei    = d_in[1];
    const void*  batch = d_in[2];
    const float* w1    = (const float*)d_in[3];
    const float* b1    = (const float*)d_in[4];
    const float* w2    = (const float*)d_in[5];
    const float* b2    = (const float*)d_in[6];
    const float* wlin  = (const float*)d_in[7];
    const float* blin  = (const float*)d_in[8];
    float* out = (float*)d_out;

    int n  = in_sizes[0] / DD;      // 50000 nodes
    int ne = in_sizes[1] / 2;       // 640000 edges
    if (n > NODES_MAX) n = NODES_MAX;

    float *pA, *pB, *pPool, *pCnt, *pScratch;
    cudaGetSymbolAddress((void**)&pA, g_bufA);
    cudaGetSymbolAddress((void**)&pB, g_bufB);
    cudaGetSymbolAddress((void**)&pPool, g_pool);
    cudaGetSymbolAddress((void**)&pCnt, g_cnt);
    cudaGetSymbolAddress((void**)&pScratch, g_scratch);

    cudaFuncSetAttribute(mlp_kernel, cudaFuncAttributeMaxDynamicSharedMemorySize, SMEM_BYTES);

    const int scatter_grid = (ne * 32 + 255) / 256;
    const int mlp_grid     = (n + BM - 1) / BM;
    const int pool_grid    = (n * 32 + 255) / 256;
    const size_t hbytes    = (size_t)n * DD * sizeof(float);

    detect_kernel<<<1, 32>>>((const int*)ei);

    const float* hcur = x;
    for (int L = 0; L < 4; ++L) {
        cudaMemcpyAsync(pB, hcur, hbytes, cudaMemcpyDeviceToDevice, 0);
        scatter_kernel<<<scatter_grid, 256>>>(hcur, ei, pB, ne, n);
        mlp_kernel<<<mlp_grid, TB, SMEM_BYTES>>>(
            pB, w1 + (size_t)L * DD * DD, b1 + (size_t)L * DD,
            w2 + (size_t)L * DD * DD, b2 + (size_t)L * DD,
            pA, n, (L < 3) ? 1 : 0);
        hcur = pA;
    }

    zero_pool_kernel<<<(NGRAPH * DD + 255) / 256, 256>>>(pPool, pCnt);
    pool_kernel<<<pool_grid, 256>>>(pA, batch, pPool, pCnt, n);

    // output layout adaptive to out_size: expected 10240 = 64*128 pooled || 64*32 logits
    float* out_pooled = pScratch;
    float* out_logits = pScratch + NGRAPH * DD;
    if (out_size >= NGRAPH * DD + NGRAPH * NCLASS) {
        out_pooled = out;
        out_logits = out + NGRAPH * DD;
    } else if (out_size == NGRAPH * NCLASS) {
        out_logits = out;
    } else if (out_size == NGRAPH * DD) {
        out_pooled = out;
    }
    finalize_kernel<<<NGRAPH, DD>>>(pPool, pCnt, wlin, blin, out_pooled, out_logits);
}

// round 4
// speedup vs baseline: 1.9933x; 1.4609x over previous
#include <cuda_runtime.h>
#include <cstdint>

#define DD 128
#define NODES_MAX 50000
#define NE_MAX 640000
#define NGRAPH 64
#define NCLASS 32
#define BM 128
#define TB 512
#define SA 132                       // padded row stride for transposed smem tiles
#define SMEM_FLOATS (2*DD*DD + DD*SA)
#define SMEM_BYTES (SMEM_FLOATS * 4)

__device__ float g_bufA[NODES_MAX * DD];
__device__ float g_bufB[NODES_MAX * DD];
__device__ float g_pool[NGRAPH * DD];
__device__ float g_cnt[NGRAPH];
__device__ float g_scratch[NGRAPH * DD + NGRAPH * NCLASS];
__device__ int   g_is64;
__device__ int   g_deg[NODES_MAX];
__device__ int   g_off[NODES_MAX + 1];
__device__ int   g_cur[NODES_MAX];
__device__ int   g_esrc[NE_MAX];

// ---------- packed f32x2 helpers ----------
__device__ __forceinline__ unsigned long long splat2(float x) {
    unsigned long long r;
    asm("mov.b64 %0, {%1, %1};" : "=l"(r) : "f"(x));
    return r;
}
__device__ __forceinline__ void fma2(unsigned long long& acc, unsigned long long a, unsigned long long b) {
    asm("fma.rn.f32x2 %0, %1, %2, %0;" : "+l"(acc) : "l"(a), "l"(b));
}
__device__ __forceinline__ void add2(unsigned long long& acc, unsigned long long a) {
    asm("add.rn.f32x2 %0, %1, %0;" : "+l"(acc) : "l"(a));
}
__device__ __forceinline__ float lo32(unsigned long long v) { return __uint_as_float((unsigned)(v & 0xffffffffull)); }
__device__ __forceinline__ float hi32(unsigned long long v) { return __uint_as_float((unsigned)(v >> 32)); }

__device__ __forceinline__ void red_add_v4(float* p, float4 v) {
    asm volatile("red.global.add.v4.f32 [%0], {%1, %2, %3, %4};"
                 :: "l"(p), "f"(v.x), "f"(v.y), "f"(v.z), "f"(v.w) : "memory");
}

// ---------- dtype detection: int64 viewed as int32 has odd words == 0 ----------
__global__ void detect_kernel(const int* __restrict__ idx32) {
    if (threadIdx.x == 0 && blockIdx.x == 0) {
        int is64 = 1;
        #pragma unroll 1
        for (int i = 1; i < 128; i += 2)
            if (idx32[i] != 0) { is64 = 0; break; }
        g_is64 = is64;
    }
}

__device__ __forceinline__ int load_idx(const void* p, int i, int is64) {
    if (is64) return (int)((const long long*)p)[i];
    return ((const int*)p)[i];
}

// ================= CSR build =================
__global__ void hist_kernel(const void* __restrict__ ei, int* __restrict__ deg, int ne, int n) {
    int e = blockIdx.x * blockDim.x + threadIdx.x;
    if (e >= ne) return;
    const int is64 = g_is64;
    int s = load_idx(ei, e, is64);
    int d = load_idx(ei, ne + e, is64);
    if ((unsigned)s >= (unsigned)n || (unsigned)d >= (unsigned)n) return;
    atomicAdd(deg + d, 1);
}

__global__ void scan_kernel(const int* __restrict__ deg, int* __restrict__ off, int n) {
    __shared__ int part[1024];
    const int tid = threadIdx.x;
    const int chunk = (n + 1023) >> 10;
    const int st = tid * chunk;
    int s = 0;
    for (int i = 0; i < chunk; ++i) { int j = st + i; if (j < n) s += deg[j]; }
    part[tid] = s;
    __syncthreads();
    for (int d = 1; d < 1024; d <<= 1) {
        int v = (tid >= d) ? part[tid - d] : 0;
        __syncthreads();
        part[tid] += v;
        __syncthreads();
    }
    int run = tid ? part[tid - 1] : 0;
    for (int i = 0; i < chunk; ++i) {
        int j = st + i;
        if (j < n) { off[j] = run; run += deg[j]; }
    }
    if (tid == 1023) off[n] = part[1023];
}

__global__ void curinit_kernel(const int* __restrict__ off, int* __restrict__ cur, int n) {
    int i = blockIdx.x * blockDim.x + threadIdx.x;
    if (i < n) cur[i] = off[i];
}

__global__ void fill_kernel(const void* __restrict__ ei, int* __restrict__ cur,
                            int* __restrict__ esrc, int ne, int n) {
    int e = blockIdx.x * blockDim.x + threadIdx.x;
    if (e >= ne) return;
    const int is64 = g_is64;
    int s = load_idx(ei, e, is64);
    int d = load_idx(ei, ne + e, is64);
    if ((unsigned)s >= (unsigned)n || (unsigned)d >= (unsigned)n) return;
    int pos = atomicAdd(cur + d, 1);
    esrc[pos] = s;
}

// ================= gather: out[v] = h[v] + sum_{u in N(v)} h[u] =================
__global__ void gather_kernel(const float* __restrict__ h, const int* __restrict__ off,
                              const int* __restrict__ esrc, float* __restrict__ out, int n) {
    int node = (blockIdx.x * blockDim.x + threadIdx.x) >> 5;
    int lane = threadIdx.x & 31;
    if (node >= n) return;
    int beg = off[node], end = off[node + 1];
    float4 a = *(const float4*)(h + (size_t)node * DD + lane * 4);
    #pragma unroll 1
    for (int e = beg; e < end; ++e) {
        int s = esrc[e];
        float4 v = *(const float4*)(h + (size_t)s * DD + lane * 4);
        a.x += v.x; a.y += v.y; a.z += v.z; a.w += v.w;
    }
    *(float4*)(out + (size_t)node * DD + lane * 4) = a;
}

// ---------- fused MLP: out = [relu]( relu(in@W1+b1) @ W2 + b2 ), 512 thr, split-k ----------
__global__ void __launch_bounds__(TB, 1)
mlp_kernel(const float* __restrict__ in, const float* __restrict__ w1,
           const float* __restrict__ b1, const float* __restrict__ w2,
           const float* __restrict__ b2, float* __restrict__ out,
           int n, int relu_out)
{
    extern __shared__ float sm[];
    float* w1s = sm;                 // DD*DD (reused as reduction buffer post-stage1)
    float* w2s = sm + DD * DD;       // DD*DD
    float* ts  = sm + 2 * DD * DD;   // transposed tile: ts[k*SA + r]
    unsigned long long* red = (unsigned long long*)w1s;  // 8192 u64 = 64KB

    const int tid = threadIdx.x;

    // load both weight matrices (16384 floats each)
    #pragma unroll
    for (int i = 0; i < DD * DD; i += TB * 4) {
        int idx = i + tid * 4;
        *(float4*)(w1s + idx) = *(const float4*)(w1 + idx);
        *(float4*)(w2s + idx) = *(const float4*)(w2 + idx);
    }

    // load input tile transposed: ts[c][r]
    const int row0 = blockIdx.x * BM;
    #pragma unroll
    for (int i = tid; i < BM * (DD / 4); i += TB) {
        int r = i >> 5;             // DD/4 == 32 float4 per row
        int c = (i & 31) * 4;
        float4 v = make_float4(0.f, 0.f, 0.f, 0.f);
        if (row0 + r < n) v = *(const float4*)(in + (size_t)(row0 + r) * DD + c);
        ts[(c + 0) * SA + r] = v.x;
        ts[(c + 1) * SA + r] = v.y;
        ts[(c + 2) * SA + r] = v.z;
        ts[(c + 3) * SA + r] = v.w;
    }
    __syncthreads();

    const int kh = tid >> 8;         // k-half: 0 or 1
    const int t  = tid & 255;        // spatial tile id
    const int rb = (t & 15) * 8;     // row offset (8 rows = 4 f32x2 pairs)
    const int cb = (t >> 4) * 8;     // col offset (8 cols)
    const int k0 = kh * 64;

    unsigned long long acc[4][8];

    // ================= stage 1: z = relu(in @ W1 + b1) =================
    #pragma unroll
    for (int i = 0; i < 4; i++)
        #pragma unroll
        for (int j = 0; j < 8; j++) acc[i][j] = 0ull;

    #pragma unroll 2
    for (int k = k0; k < k0 + 64; ++k) {
        const float* tk = ts + k * SA + rb;
        ulonglong2 aA = *(const ulonglong2*)(tk);
        ulonglong2 aB = *(const ulonglong2*)(tk + 4);
        unsigned long long ap[4] = { aA.x, aA.y, aB.x, aB.y };
        const float4 bv0 = *(const float4*)(w1s + k * DD + cb);
        const float4 bv1 = *(const float4*)(w1s + k * DD + cb + 4);
        unsigned long long bs[8] = { splat2(bv0.x), splat2(bv0.y), splat2(bv0.z), splat2(bv0.w),
                                     splat2(bv1.x), splat2(bv1.y), splat2(bv1.z), splat2(bv1.w) };
        #pragma unroll
        for (int i = 0; i < 4; i++)
            #pragma unroll
            for (int j = 0; j < 8; j++)
                fma2(acc[i][j], ap[i], bs[j]);
    }
    __syncthreads();   // ts & w1s reads done

    // cross-k reduction through smem (w1s region)
    if (kh == 1) {
        #pragma unroll
        for (int i = 0; i < 4; i++)
            #pragma unroll
            for (int j = 0; j < 8; j++)
                red[((i * 8 + j) << 8) + t] = acc[i][j];
    }
    __syncthreads();
    if (kh == 0) {
        #pragma unroll
        for (int i = 0; i < 4; i++)
            #pragma unroll
            for (int j = 0; j < 8; j++)
                add2(acc[i][j], red[((i * 8 + j) << 8) + t]);

        // epilogue 1: bias + relu, write z transposed back into ts
        #pragma unroll
        for (int j = 0; j < 8; ++j) {
            float bj = b1[cb + j];
            float4 v0, v1;
            v0.x = fmaxf(lo32(acc[0][j]) + bj, 0.f);
            v0.y = fmaxf(hi32(acc[0][j]) + bj, 0.f);
            v0.z = fmaxf(lo32(acc[1][j]) + bj, 0.f);
            v0.w = fmaxf(hi32(acc[1][j]) + bj, 0.f);
            v1.x = fmaxf(lo32(acc[2][j]) + bj, 0.f);
            v1.y = fmaxf(hi32(acc[2][j]) + bj, 0.f);
            v1.z = fmaxf(lo32(acc[3][j]) + bj, 0.f);
            v1.w = fmaxf(hi32(acc[3][j]) + bj, 0.f);
            *(float4*)(ts + (cb + j) * SA + rb)     = v0;
            *(float4*)(ts + (cb + j) * SA + rb + 4) = v1;
        }
    }
    __syncthreads();

    // ================= stage 2: h = z @ W2 + b2 (+relu) =================
    #pragma unroll
    for (int i = 0; i < 4; i++)
        #pragma unroll
        for (int j = 0; j < 8; j++) acc[i][j] = 0ull;

    #pragma unroll 2
    for (int k = k0; k < k0 + 64; ++k) {
        const float* tk = ts + k * SA + rb;
        ulonglong2 aA = *(const ulonglong2*)(tk);
        ulonglong2 aB = *(const ulonglong2*)(tk + 4);
        unsigned long long ap[4] = { aA.x, aA.y, aB.x, aB.y };
        const float4 bv0 = *(const float4*)(w2s + k * DD + cb);
        const float4 bv1 = *(const float4*)(w2s + k * DD + cb + 4);
        unsigned long long bs[8] = { splat2(bv0.x), splat2(bv0.y), splat2(bv0.z), splat2(bv0.w),
                                     splat2(bv1.x), splat2(bv1.y), splat2(bv1.z), splat2(bv1.w) };
        #pragma unroll
        for (int i = 0; i < 4; i++)
            #pragma unroll
            for (int j = 0; j < 8; j++)
                fma2(acc[i][j], ap[i], bs[j]);
    }
    __syncthreads();

    if (kh == 1) {
        #pragma unroll
        for (int i = 0; i < 4; i++)
            #pragma unroll
            for (int j = 0; j < 8; j++)
                red[((i * 8 + j) << 8) + t] = acc[i][j];
    }
    __syncthreads();
    if (kh == 0) {
        #pragma unroll
        for (int i = 0; i < 4; i++)
            #pragma unroll
            for (int j = 0; j < 8; j++)
                add2(acc[i][j], red[((i * 8 + j) << 8) + t]);

        // epilogue 2: bias (+relu), store to global
        float bb[8];
        #pragma unroll
        for (int j = 0; j < 8; ++j) bb[j] = b2[cb + j];

        #pragma unroll
        for (int i2 = 0; i2 < 4; ++i2) {
            float o0[8], o1[8];
            #pragma unroll
            for (int j = 0; j < 8; ++j) {
                o0[j] = lo32(acc[i2][j]) + bb[j];
                o1[j] = hi32(acc[i2][j]) + bb[j];
                if (relu_out) { o0[j] = fmaxf(o0[j], 0.f); o1[j] = fmaxf(o1[j], 0.f); }
            }
            int r0g = row0 + rb + 2 * i2;
            if (r0g < n) {
                *(float4*)(out + (size_t)r0g * DD + cb)     = make_float4(o0[0], o0[1], o0[2], o0[3]);
                *(float4*)(out + (size_t)r0g * DD + cb + 4) = make_float4(o0[4], o0[5], o0[6], o0[7]);
            }
            if (r0g + 1 < n) {
                *(float4*)(out + (size_t)(r0g + 1) * DD + cb)     = make_float4(o1[0], o1[1], o1[2], o1[3]);
                *(float4*)(out + (size_t)(r0g + 1) * DD + cb + 4) = make_float4(o1[4], o1[5], o1[6], o1[7]);
            }
        }
    }
}

// ---------- pooling ----------
__global__ void zero_pool_kernel(float* pool, float* cnt) {
    int i = blockIdx.x * blockDim.x + threadIdx.x;
    if (i < NGRAPH * DD) pool[i] = 0.f;
    if (i < NGRAPH) cnt[i] = 0.f;
}

__global__ void pool_kernel(const float* __restrict__ h, const void* __restrict__ batch,
                            float* __restrict__ pool, float* __restrict__ cnt, int n) {
    int node = (blockIdx.x * blockDim.x + threadIdx.x) >> 5;
    int lane = threadIdx.x & 31;
    if (node >= n) return;
    int g = load_idx(batch, node, g_is64);
    if ((unsigned)g >= (unsigned)NGRAPH) return;
    float4 v = *(const float4*)(h + (size_t)node * DD + lane * 4);
    red_add_v4(pool + g * DD + lane * 4, v);
    if (lane == 0) atomicAdd(cnt + g, 1.0f);
}

// ---------- finalize: pooled mean + logits ----------
__global__ void finalize_kernel(const float* __restrict__ pool, const float* __restrict__ cnt,
                                const float* __restrict__ wlin, const float* __restrict__ blin,
                                float* __restrict__ out_pooled, float* __restrict__ out_logits) {
    __shared__ float ps[DD];
    int g = blockIdx.x;
    int t = threadIdx.x;
    float c = fmaxf(cnt[g], 1.0f);
    float v = pool[g * DD + t] / c;
    ps[t] = v;
    out_pooled[g * DD + t] = v;                 // pooled output [64,128]
    __syncthreads();
    if (t < NCLASS) {
        float s = blin[t];
        #pragma unroll 4
        for (int k = 0; k < DD; ++k) s += ps[k] * wlin[k * NCLASS + t];
        out_logits[g * NCLASS + t] = s;         // logits output [64,32]
    }
}

extern "C" void kernel_launch(void* const* d_in, const int* in_sizes, int n_in,
                              void* d_out, int out_size) {
    const float* x     = (const float*)d_in[0];
    const void*  ei    = d_in[1];
    const void*  batch = d_in[2];
    const float* w1    = (const float*)d_in[3];
    const float* b1    = (const float*)d_in[4];
    const float* w2    = (const float*)d_in[5];
    const float* b2    = (const float*)d_in[6];
    const float* wlin  = (const float*)d_in[7];
    const float* blin  = (const float*)d_in[8];
    float* out = (float*)d_out;

    int n  = in_sizes[0] / DD;      // 50000 nodes
    int ne = in_sizes[1] / 2;       // 640000 edges
    if (n > NODES_MAX) n = NODES_MAX;
    if (ne > NE_MAX) ne = NE_MAX;

    float *pA, *pB, *pPool, *pCnt, *pScratch;
    int *pDeg, *pOff, *pCur, *pEsrc;
    cudaGetSymbolAddress((void**)&pA, g_bufA);
    cudaGetSymbolAddress((void**)&pB, g_bufB);
    cudaGetSymbolAddress((void**)&pPool, g_pool);
    cudaGetSymbolAddress((void**)&pCnt, g_cnt);
    cudaGetSymbolAddress((void**)&pScratch, g_scratch);
    cudaGetSymbolAddress((void**)&pDeg, g_deg);
    cudaGetSymbolAddress((void**)&pOff, g_off);
    cudaGetSymbolAddress((void**)&pCur, g_cur);
    cudaGetSymbolAddress((void**)&pEsrc, g_esrc);

    cudaFuncSetAttribute(mlp_kernel, cudaFuncAttributeMaxDynamicSharedMemorySize, SMEM_BYTES);

    const int mlp_grid  = (n + BM - 1) / BM;
    const int warp_grid = (n * 32 + 255) / 256;
    const int edge_grid = (ne + 255) / 256;

    detect_kernel<<<1, 32>>>((const int*)ei);

    // ---- CSR build (per call; edge_index is an input) ----
    cudaMemsetAsync(pDeg, 0, (size_t)n * sizeof(int), 0);
    hist_kernel<<<edge_grid, 256>>>(ei, pDeg, ne, n);
    scan_kernel<<<1, 1024>>>(pDeg, pOff, n);
    curinit_kernel<<<(n + 255) / 256, 256>>>(pOff, pCur, n);
    fill_kernel<<<edge_grid, 256>>>(ei, pCur, pEsrc, ne, n);

    const float* hcur = x;
    for (int L = 0; L < 4; ++L) {
        gather_kernel<<<warp_grid, 256>>>(hcur, pOff, pEsrc, pB, n);
        mlp_kernel<<<mlp_grid, TB, SMEM_BYTES>>>(
            pB, w1 + (size_t)L * DD * DD, b1 + (size_t)L * DD,
            w2 + (size_t)L * DD * DD, b2 + (size_t)L * DD,
            pA, n, (L < 3) ? 1 : 0);
        hcur = pA;
    }

    zero_pool_kernel<<<(NGRAPH * DD + 255) / 256, 256>>>(pPool, pCnt);
    pool_kernel<<<warp_grid, 256>>>(pA, batch, pPool, pCnt, n);

    // output layout adaptive to out_size: expected 10240 = 64*128 pooled || 64*32 logits
    float* out_pooled = pScratch;
    float* out_logits = pScratch + NGRAPH * DD;
    if (out_size >= NGRAPH * DD + NGRAPH * NCLASS) {
        out_pooled = out;
        out_logits = out + NGRAPH * DD;
    } else if (out_size == NGRAPH * NCLASS) {
        out_logits = out;
    } else if (out_size == NGRAPH * DD) {
        out_pooled = out;
    }
    finalize_kernel<<<NGRAPH, DD>>>(pPool, pCnt, wlin, blin, out_pooled, out_logits);
}

// round 7
// speedup vs baseline: 2.6727x; 1.3408x over previous
#include <cuda_runtime.h>
#include <cuda_bf16.h>
#include <cstdint>

#define DD 128
#define NODES_MAX 50000
#define NE_MAX 640000
#define NGRAPH 64
#define NCLASS 32
#define BM 128

// ---- smem layout for mma MLP (bytes from dynamic smem base) ----
#define SAB   272                    // bytes per bf16 row (136 elems) -> conflict-free ldmatrix
#define MATB  (128 * SAB)            // 34816 bytes per 128x128 bf16 matrix
#define SM_B1 0
#define SM_B2 512
#define SM_AH 1024
#define SM_AL (SM_AH + MATB)
#define SM_W  (SM_AL + MATB)         // [W1hi|W1lo|W2hi|W2lo]
#define MLP_SMEM (SM_W + 4 * MATB)   // 209920 bytes

#define WL_BYTES (4 * MATB)          // per-layer prepped weights

__device__ float g_bufA[NODES_MAX * DD];
__device__ float g_bufB[NODES_MAX * DD];
__device__ float g_pool[NGRAPH * DD];
__device__ float g_cnt[NGRAPH];
__device__ float g_scratch[NGRAPH * DD + NGRAPH * NCLASS];
__device__ int   g_is64;
__device__ int   g_deg[NODES_MAX];
__device__ int   g_off[NODES_MAX + 1];
__device__ int   g_cur[NODES_MAX];
__device__ int   g_esrc[NE_MAX];
__device__ __align__(16) unsigned char g_wprep[4 * WL_BYTES];

// ================= helpers =================
__device__ __forceinline__ void red_add_v4(float* p, float4 v) {
    asm volatile("red.global.add.v4.f32 [%0], {%1, %2, %3, %4};"
                 :: "l"(p), "f"(v.x), "f"(v.y), "f"(v.z), "f"(v.w) : "memory");
}
__device__ __forceinline__ uint32_t smem_u32(const void* p) {
    uint32_t a;
    asm("{ .reg .u64 t; cvta.to.shared.u64 t, %1; cvt.u32.u64 %0, t; }" : "=r"(a) : "l"(p));
    return a;
}
__device__ __forceinline__ unsigned short f2bf(float x) {
    return __bfloat16_as_ushort(__float2bfloat16_rn(x));
}
__device__ __forceinline__ float bf2f(unsigned short u) {
    return __bfloat162float(__ushort_as_bfloat16(u));
}
__device__ __forceinline__ void ldsm_x4(uint32_t* r, uint32_t addr) {
    asm volatile("ldmatrix.sync.aligned.m8n8.x4.shared.b16 {%0,%1,%2,%3}, [%4];"
                 : "=r"(r[0]), "=r"(r[1]), "=r"(r[2]), "=r"(r[3]) : "r"(addr));
}
__device__ __forceinline__ void mma_bf16(float* d, const uint32_t* a, const uint32_t* b) {
    asm volatile("mma.sync.aligned.m16n8k16.row.col.f32.bf16.bf16.f32 "
                 "{%0,%1,%2,%3}, {%4,%5,%6,%7}, {%8,%9}, {%0,%1,%2,%3};"
                 : "+f"(d[0]), "+f"(d[1]), "+f"(d[2]), "+f"(d[3])
                 : "r"(a[0]), "r"(a[1]), "r"(a[2]), "r"(a[3]), "r"(b[0]), "r"(b[1]));
}

// ---------- dtype detection: int64 viewed as int32 has odd words == 0 ----------
__global__ void detect_kernel(const int* __restrict__ idx32) {
    if (threadIdx.x == 0 && blockIdx.x == 0) {
        int is64 = 1;
        #pragma unroll 1
        for (int i = 1; i < 128; i += 2)
            if (idx32[i] != 0) { is64 = 0; break; }
        g_is64 = is64;
    }
}
__device__ __forceinline__ int load_idx(const void* p, int i, int is64) {
    if (is64) return (int)((const long long*)p)[i];
    return ((const int*)p)[i];
}

// ===== weight prep: fp32 W[k][n] -> bf16 hi/lo, stored transposed [n][k], padded rows =====
__global__ void wprep_kernel(const float* __restrict__ w1, const float* __restrict__ w2) {
    int idx = blockIdx.x * blockDim.x + threadIdx.x;   // 4 layers * 2 mats * 16384
    if (idx >= 4 * 2 * DD * DD) return;
    int l = idx / (2 * DD * DD);
    int rem = idx % (2 * DD * DD);
    int m = rem / (DD * DD);
    int kn = rem % (DD * DD);
    int k = kn / DD, nn = kn % DD;
    const float* w = m ? w2 : w1;
    float v = w[(size_t)l * DD * DD + k * DD + nn];
    unsigned short hi = f2bf(v);
    unsigned short lo = f2bf(v - bf2f(hi));
    unsigned char* base = g_wprep + (size_t)l * WL_BYTES + (size_t)m * (2 * MATB);
    uint32_t a = (uint32_t)nn * SAB + (uint32_t)k * 2;
    *(unsigned short*)(base + a)        = hi;
    *(unsigned short*)(base + MATB + a) = lo;
}

// ================= CSR build =================
__global__ void hist_kernel(const void* __restrict__ ei, int* __restrict__ deg, int ne, int n) {
    int e = blockIdx.x * blockDim.x + threadIdx.x;
    if (e >= ne) return;
    const int is64 = g_is64;
    int s = load_idx(ei, e, is64);
    int d = load_idx(ei, ne + e, is64);
    if ((unsigned)s >= (unsigned)n || (unsigned)d >= (unsigned)n) return;
    atomicAdd(deg + d, 1);
}

__global__ void scan_kernel(const int* __restrict__ deg, int* __restrict__ off,
                            int* __restrict__ cur, int n) {
    __shared__ int part[1024];
    const int tid = threadIdx.x;
    const int chunk = (n + 1023) >> 10;
    const int st = tid * chunk;
    int s = 0;
    for (int i = 0; i < chunk; ++i) { int j = st + i; if (j < n) s += deg[j]; }
    part[tid] = s;
    __syncthreads();
    for (int d = 1; d < 1024; d <<= 1) {
        int v = (tid >= d) ? part[tid - d] : 0;
        __syncthreads();
        part[tid] += v;
        __syncthreads();
    }
    int run = tid ? part[tid - 1] : 0;
    for (int i = 0; i < chunk; ++i) {
        int j = st + i;
        if (j < n) { off[j] = run; cur[j] = run; run += deg[j]; }
    }
    if (tid == 1023) off[n] = part[1023];
}

__global__ void fill_kernel(const void* __restrict__ ei, int* __restrict__ cur,
                            int* __restrict__ esrc, int ne, int n) {
    int e = blockIdx.x * blockDim.x + threadIdx.x;
    if (e >= ne) return;
    const int is64 = g_is64;
    int s = load_idx(ei, e, is64);
    int d = load_idx(ei, ne + e, is64);
    if ((unsigned)s >= (unsigned)n || (unsigned)d >= (unsigned)n) return;
    int pos = atomicAdd(cur + d, 1);
    esrc[pos] = s;
}

// ================= gather: out[v] = h[v] + sum_{u in N(v)} h[u] =================
__global__ void gather_kernel(const float* __restrict__ h, const int* __restrict__ off,
                              const int* __restrict__ esrc, float* __restrict__ out, int n) {
    int node = (blockIdx.x * blockDim.x + threadIdx.x) >> 5;
    int lane = threadIdx.x & 31;
    if (node >= n) return;
    int beg = off[node], end = off[node + 1];
    float4 a = *(const float4*)(h + (size_t)node * DD + lane * 4);
    #pragma unroll 1
    for (int e = beg; e < end; ++e) {
        int s = esrc[e];
        float4 v = *(const float4*)(h + (size_t)s * DD + lane * 4);
        a.x += v.x; a.y += v.y; a.z += v.z; a.w += v.w;
    }
    *(float4*)(out + (size_t)node * DD + lane * 4) = a;
}

// ================= MLP via mma.sync bf16 (3-term hi/lo split) =================
__device__ __forceinline__ void gemm_stage(uint32_t ah0, uint32_t al0,
                                           uint32_t bh_base, uint32_t bl_base,
                                           float acc[2][8][4]) {
    #pragma unroll 1
    for (int kk = 0; kk < 8; ++kk) {
        uint32_t ah[2][4], al[2][4];
        ldsm_x4(ah[0], ah0 + kk * 32);
        ldsm_x4(ah[1], ah0 + 16 * SAB + kk * 32);
        ldsm_x4(al[0], al0 + kk * 32);
        ldsm_x4(al[1], al0 + 16 * SAB + kk * 32);
        #pragma unroll
        for (int np = 0; np < 4; ++np) {
            uint32_t bh[4], bl[4];
            ldsm_x4(bh, bh_base + np * 16 * SAB + kk * 32);
            ldsm_x4(bl, bl_base + np * 16 * SAB + kk * 32);
            #pragma unroll
            for (int t = 0; t < 2; ++t) {
                #pragma unroll
                for (int mt = 0; mt < 2; ++mt) {
                    float* d = acc[mt][2 * np + t];
                    mma_bf16(d, ah[mt], &bh[2 * t]);
                    mma_bf16(d, ah[mt], &bl[2 * t]);
                    mma_bf16(d, al[mt], &bh[2 * t]);
                }
            }
        }
    }
}

__global__ void __launch_bounds__(256, 1)
mlp_mma_kernel(const float* __restrict__ in, const unsigned char* __restrict__ wprep,
               const float* __restrict__ b1, const float* __restrict__ b2,
               float* __restrict__ out, int n, int relu_out)
{
    extern __shared__ char smc[];
    const uint32_t sb = smem_u32(smc);

    const int tid = threadIdx.x;
    const int wid = tid >> 5;
    const int lane = tid & 31;
    const int rg = wid >> 1;          // warp row group (0..3): rows rg*32..+31
    const int cg = wid & 1;           // warp col group (0..1): cols cg*64..+63
    const int row0 = blockIdx.x * BM;

    // ---- copy prepped weights for this layer (exact smem image) ----
    {
        const uint4* wsrc = (const uint4*)wprep;
        uint4* wdst = (uint4*)(smc + SM_W);
        #pragma unroll 8
        for (int i = tid; i < WL_BYTES / 16; i += 256) wdst[i] = wsrc[i];
    }
    // ---- biases ----
    if (tid < DD) {
        ((float*)(smc + SM_B1))[tid] = b1[tid];
        ((float*)(smc + SM_B2))[tid] = b2[tid];
    }
    // ---- load A tile, split bf16 hi/lo ----
    {
        int r = tid >> 1;
        int c0 = (tid & 1) * 64;
        bool valid = (row0 + r) < n;
        const float* src = in + (size_t)(row0 + r) * DD + c0;
        char* ah = smc + SM_AH + r * SAB + c0 * 2;
        char* al = smc + SM_AL + r * SAB + c0 * 2;
        #pragma unroll
        for (int c = 0; c < 64; c += 4) {
            float4 v = valid ? *(const float4*)(src + c) : make_float4(0.f, 0.f, 0.f, 0.f);
            unsigned short h0 = f2bf(v.x), h1 = f2bf(v.y), h2 = f2bf(v.z), h3 = f2bf(v.w);
            unsigned short l0 = f2bf(v.x - bf2f(h0)), l1 = f2bf(v.y - bf2f(h1));
            unsigned short l2 = f2bf(v.z - bf2f(h2)), l3 = f2bf(v.w - bf2f(h3));
            *(uint2*)(ah + c * 2) = make_uint2((uint32_t)h0 | ((uint32_t)h1 << 16),
                                               (uint32_t)h2 | ((uint32_t)h3 << 16));
            *(uint2*)(al + c * 2) = make_uint2((uint32_t)l0 | ((uint32_t)l1 << 16),
                                               (uint32_t)l2 | ((uint32_t)l3 << 16));
        }
    }
    __syncthreads();

    // per-lane ldmatrix offsets
    // A: row = rg*32 + mt*16 + (lane&15); col8 = (lane>>4)*8
    const uint32_t a_off = (uint32_t)(rg * 32 + (lane & 15)) * SAB + ((lane >> 4) << 3) * 2;
    const uint32_t ah0 = sb + SM_AH + a_off;
    const uint32_t al0 = sb + SM_AL + a_off;
    // B (weights [n][k]): g=lane>>3, i=lane&7; row(n) = cg*64 + (g>>1)*8 + i; col8(k) = (g&1)*8
    {
        const int g = lane >> 3, ii = lane & 7;
        const uint32_t b_off = (uint32_t)(cg * 64 + ((g >> 1) << 3) + ii) * SAB + ((g & 1) << 3) * 2;

        float acc[2][8][4];

        // ======== stage 1: D1 = A @ W1 ========
        #pragma unroll
        for (int mt = 0; mt < 2; ++mt)
            #pragma unroll
            for (int nt = 0; nt < 8; ++nt)
                #pragma unroll
                for (int q = 0; q < 4; ++q) acc[mt][nt][q] = 0.f;

        gemm_stage(ah0, al0, sb + SM_W + b_off, sb + SM_W + MATB + b_off, acc);
        __syncthreads();   // all A reads done before overwrite

        // epilogue 1: z = relu(D1 + b1) -> bf16 hi/lo back into A
        {
            const float* sb1 = (const float*)(smc + SM_B1);
            const int qr = lane >> 2;
            const int qc = (lane & 3) * 2;
            #pragma unroll
            for (int mt = 0; mt < 2; ++mt) {
                #pragma unroll
                for (int nt = 0; nt < 8; ++nt) {
                    int row = rg * 32 + mt * 16 + qr;
                    int col = cg * 64 + nt * 8 + qc;
                    float bj0 = sb1[col], bj1 = sb1[col + 1];
                    float z0 = fmaxf(acc[mt][nt][0] + bj0, 0.f);
                    float z1 = fmaxf(acc[mt][nt][1] + bj1, 0.f);
                    float z2 = fmaxf(acc[mt][nt][2] + bj0, 0.f);
                    float z3 = fmaxf(acc[mt][nt][3] + bj1, 0.f);
                    unsigned short h0 = f2bf(z0), h1 = f2bf(z1), h2 = f2bf(z2), h3 = f2bf(z3);
                    unsigned short l0 = f2bf(z0 - bf2f(h0)), l1 = f2bf(z1 - bf2f(h1));
                    unsigned short l2 = f2bf(z2 - bf2f(h2)), l3 = f2bf(z3 - bf2f(h3));
                    uint32_t o0 = (uint32_t)row * SAB + (uint32_t)col * 2;
                    uint32_t o1 = (uint32_t)(row + 8) * SAB + (uint32_t)col * 2;
                    *(uint32_t*)(smc + SM_AH + o0) = (uint32_t)h0 | ((uint32_t)h1 << 16);
                    *(uint32_t*)(smc + SM_AH + o1) = (uint32_t)h2 | ((uint32_t)h3 << 16);
                    *(uint32_t*)(smc + SM_AL + o0) = (uint32_t)l0 | ((uint32_t)l1 << 16);
                    *(uint32_t*)(smc + SM_AL + o1) = (uint32_t)l2 | ((uint32_t)l3 << 16);
                }
            }
        }
        __syncthreads();

        // ======== stage 2: D2 = Z @ W2 ========
        #pragma unroll
        for (int mt = 0; mt < 2; ++mt)
            #pragma unroll
            for (int nt = 0; nt < 8; ++nt)
                #pragma unroll
                for (int q = 0; q < 4; ++q) acc[mt][nt][q] = 0.f;

        gemm_stage(ah0, al0, sb + SM_W + 2 * MATB + b_off, sb + SM_W + 3 * MATB + b_off, acc);

        // epilogue 2: out = D2 + b2 (+relu)
        {
            const float* sb2 = (const float*)(smc + SM_B2);
            const int qr = lane >> 2;
            const int qc = (lane & 3) * 2;
            #pragma unroll
            for (int mt = 0; mt < 2; ++mt) {
                int row = rg * 32 + mt * 16 + qr;
                int grow0 = row0 + row;
                int grow1 = grow0 + 8;
                #pragma unroll
                for (int nt = 0; nt < 8; ++nt) {
                    int col = cg * 64 + nt * 8 + qc;
                    float bj0 = sb2[col], bj1 = sb2[col + 1];
                    float o0 = acc[mt][nt][0] + bj0;
                    float o1 = acc[mt][nt][1] + bj1;
                    float o2 = acc[mt][nt][2] + bj0;
                    float o3 = acc[mt][nt][3] + bj1;
                    if (relu_out) {
                        o0 = fmaxf(o0, 0.f); o1 = fmaxf(o1, 0.f);
                        o2 = fmaxf(o2, 0.f); o3 = fmaxf(o3, 0.f);
                    }
                    if (grow0 < n) *(float2*)(out + (size_t)grow0 * DD + col) = make_float2(o0, o1);
                    if (grow1 < n) *(float2*)(out + (size_t)grow1 * DD + col) = make_float2(o2, o3);
                }
            }
        }
    }
}

// ---------- pooling ----------
__global__ void zero_pool_kernel(float* pool, float* cnt) {
    int i = blockIdx.x * blockDim.x + threadIdx.x;
    if (i < NGRAPH * DD) pool[i] = 0.f;
    if (i < NGRAPH) cnt[i] = 0.f;
}

__global__ void pool_kernel(const float* __restrict__ h, const void* __restrict__ batch,
                            float* __restrict__ pool, float* __restrict__ cnt, int n) {
    int node = (blockIdx.x * blockDim.x + threadIdx.x) >> 5;
    int lane = threadIdx.x & 31;
    if (node >= n) return;
    int g = load_idx(batch, node, g_is64);
    if ((unsigned)g >= (unsigned)NGRAPH) return;
    float4 v = *(const float4*)(h + (size_t)node * DD + lane * 4);
    red_add_v4(pool + g * DD + lane * 4, v);
    if (lane == 0) atomicAdd(cnt + g, 1.0f);
}

// ---------- finalize: pooled mean + logits ----------
__global__ void finalize_kernel(const float* __restrict__ pool, const float* __restrict__ cnt,
                                const float* __restrict__ wlin, const float* __restrict__ blin,
                                float* __restrict__ out_pooled, float* __restrict__ out_logits) {
    __shared__ float ps[DD];
    int g = blockIdx.x;
    int t = threadIdx.x;
    float c = fmaxf(cnt[g], 1.0f);
    float v = pool[g * DD + t] / c;
    ps[t] = v;
    out_pooled[g * DD + t] = v;
    __syncthreads();
    if (t < NCLASS) {
        float s = blin[t];
        #pragma unroll 4
        for (int k = 0; k < DD; ++k) s += ps[k] * wlin[k * NCLASS + t];
        out_logits[g * NCLASS + t] = s;
    }
}

extern "C" void kernel_launch(void* const* d_in, const int* in_sizes, int n_in,
                              void* d_out, int out_size) {
    const float* x     = (const float*)d_in[0];
    const void*  ei    = d_in[1];
    const void*  batch = d_in[2];
    const float* w1    = (const float*)d_in[3];
    const float* b1    = (const float*)d_in[4];
    const float* w2    = (const float*)d_in[5];
    const float* b2    = (const float*)d_in[6];
    const float* wlin  = (const float*)d_in[7];
    const float* blin  = (const float*)d_in[8];
    float* out = (float*)d_out;

    int n  = in_sizes[0] / DD;
    int ne = in_sizes[1] / 2;
    if (n > NODES_MAX) n = NODES_MAX;
    if (ne > NE_MAX) ne = NE_MAX;

    float *pA, *pB, *pPool, *pCnt, *pScratch;
    int *pDeg, *pOff, *pCur, *pEsrc;
    unsigned char* pW;
    cudaGetSymbolAddress((void**)&pA, g_bufA);
    cudaGetSymbolAddress((void**)&pB, g_bufB);
    cudaGetSymbolAddress((void**)&pPool, g_pool);
    cudaGetSymbolAddress((void**)&pCnt, g_cnt);
    cudaGetSymbolAddress((void**)&pScratch, g_scratch);
    cudaGetSymbolAddress((void**)&pDeg, g_deg);
    cudaGetSymbolAddress((void**)&pOff, g_off);
    cudaGetSymbolAddress((void**)&pCur, g_cur);
    cudaGetSymbolAddress((void**)&pEsrc, g_esrc);
    cudaGetSymbolAddress((void**)&pW, g_wprep);

    cudaFuncSetAttribute(mlp_mma_kernel, cudaFuncAttributeMaxDynamicSharedMemorySize, MLP_SMEM);

    const int mlp_grid  = (n + BM - 1) / BM;
    const int warp_grid = (n * 32 + 255) / 256;
    const int edge_grid = (ne + 255) / 256;

    detect_kernel<<<1, 32>>>((const int*)ei);
    wprep_kernel<<<(4 * 2 * DD * DD + 255) / 256, 256>>>(w1, w2);

    // ---- CSR build ----
    cudaMemsetAsync(pDeg, 0, (size_t)n * sizeof(int), 0);
    hist_kernel<<<edge_grid, 256>>>(ei, pDeg, ne, n);
    scan_kernel<<<1, 1024>>>(pDeg, pOff, pCur, n);
    fill_kernel<<<edge_grid, 256>>>(ei, pCur, pEsrc, ne, n);

    const float* hcur = x;
    for (int L = 0; L < 4; ++L) {
        gather_kernel<<<warp_grid, 256>>>(hcur, pOff, pEsrc, pB, n);
        mlp_mma_kernel<<<mlp_grid, 256, MLP_SMEM>>>(
            pB, pW + (size_t)L * WL_BYTES, b1 + (size_t)L * DD, b2 + (size_t)L * DD,
            pA, n, (L < 3) ? 1 : 0);
        hcur = pA;
    }

    zero_pool_kernel<<<(NGRAPH * DD + 255) / 256, 256>>>(pPool, pCnt);
    pool_kernel<<<warp_grid, 256>>>(pA, batch, pPool, pCnt, n);

    float* out_pooled = pScratch;
    float* out_logits = pScratch + NGRAPH * DD;
    if (out_size >= NGRAPH * DD + NGRAPH * NCLASS) {
        out_pooled = out;
        out_logits = out + NGRAPH * DD;
    } else if (out_size == NGRAPH * NCLASS) {
        out_logits = out;
    } else if (out_size == NGRAPH * DD) {
        out_pooled = out;
    }
    finalize_kernel<<<NGRAPH, DD>>>(pPool, pCnt, wlin, blin, out_pooled, out_logits);
}